// round 2
// baseline (speedup 1.0000x reference)
#include <cuda_runtime.h>
#include <cuda_bf16.h>

// Problem constants
#define EMBED_DIM   256
#define D4          64          // EMBED_DIM / 4 (float4 chunks per row)
#define BATCH       8192
#define L_NODE      16
#define L_EDGE      15
#define L_TOTAL     47          // 16 + 15 + 16
#define NNZ         8
#define ROWS_PER_BLOCK 16

// Precomputed positional-encoding table: 16 positions x 256 dims (16 KB).
__device__ float g_pe[L_NODE * EMBED_DIM];

// Tiny pre-kernel: 16 blocks x 128 threads, each thread one (sin, cos) pair.
__global__ void pe_init_kernel() {
    const int l = blockIdx.x;        // 0..15
    const int j = threadIdx.x;       // 0..127  -> dim pair (2j, 2j+1)
    const float k = 9.210340371976184f / 256.0f;   // ln(10000)/256
    float div = __expf(-(float)(2 * j) * k);
    float s, c;
    sincosf((float)l * div, &s, &c);
    g_pe[l * EMBED_DIM + 2 * j]     = s;
    g_pe[l * EMBED_DIM + 2 * j + 1] = c;
}

__device__ __forceinline__ float4 f4_add(float4 a, float4 b) {
    return make_float4(a.x + b.x, a.y + b.y, a.z + b.z, a.w + b.w);
}

__global__ __launch_bounds__(256, 8)
void embed_kernel(const int*    __restrict__ node_idx,   // [16, 8192]
                  const int*    __restrict__ edge_idx,   // [15, 8192]
                  const int*    __restrict__ val_idx,    // [16*8192, 8]
                  const float*  __restrict__ val_w,      // [16*8192, 8]
                  const float4* __restrict__ node_tab,   // [128, 64]
                  const float4* __restrict__ edge_tab,   // [32, 64]
                  const float4* __restrict__ val_tab,    // [10000, 64]
                  float4*       __restrict__ out)        // [47, 8192, 64]
{
    const int l     = blockIdx.y;                 // 0..46
    const int col4  = threadIdx.x & 63;           // float4 column within row
    const int lrow  = threadIdx.x >> 6;           // 0..3 local row
    const int bbase = blockIdx.x * ROWS_PER_BLOCK;

    int pos, sec;
    if (l < L_NODE)                { sec = 0; pos = l; }
    else if (l < L_NODE + L_EDGE)  { sec = 1; pos = l - L_NODE; }
    else                           { sec = 2; pos = l - (L_NODE + L_EDGE); }

    // PE chunk for this (pos, col4) — broadcast L1/L2 hit.
    const float4 pe = reinterpret_cast<const float4*>(g_pe)[pos * D4 + col4];

    float4* outsec = out + (size_t)l * BATCH * D4;

    if (sec == 0 || sec == 1) {
        const int*    idxrow = (sec == 0 ? node_idx : edge_idx) + pos * BATCH;
        const float4* tab    = (sec == 0 ? node_tab : edge_tab);
        // Hoist all 4 idx loads (MLP 4 on the dependency chain).
        int idx[ROWS_PER_BLOCK / 4];
        #pragma unroll
        for (int rr = 0; rr < ROWS_PER_BLOCK / 4; rr++)
            idx[rr] = __ldg(idxrow + bbase + rr * 4 + lrow);
        #pragma unroll
        for (int rr = 0; rr < ROWS_PER_BLOCK / 4; rr++) {
            const int b = bbase + rr * 4 + lrow;
            float4 v = __ldg(tab + idx[rr] * D4 + col4);
            outsec[(size_t)b * D4 + col4] = f4_add(v, pe);
        }
    } else {
        // Val section: process rows in pairs; vectorized idx/w loads.
        #pragma unroll
        for (int rr = 0; rr < 2; rr++) {
            const int b0 = bbase + rr * 8 + lrow;      // rows b0 and b0+4
            const int b1 = b0 + 4;
            const int n0 = pos * BATCH + b0;
            const int n1 = pos * BATCH + b1;
            const int4*   ip0 = (const int4*)  (val_idx + (size_t)n0 * NNZ);
            const int4*   ip1 = (const int4*)  (val_idx + (size_t)n1 * NNZ);
            const float4* wp0 = (const float4*)(val_w   + (size_t)n0 * NNZ);
            const float4* wp1 = (const float4*)(val_w   + (size_t)n1 * NNZ);

            const int4   ia0 = __ldg(ip0),     ib0 = __ldg(ip0 + 1);
            const int4   ia1 = __ldg(ip1),     ib1 = __ldg(ip1 + 1);
            const float4 wa0 = __ldg(wp0),     wb0 = __ldg(wp0 + 1);
            const float4 wa1 = __ldg(wp1),     wb1 = __ldg(wp1 + 1);

            const int   i0[NNZ] = {ia0.x, ia0.y, ia0.z, ia0.w, ib0.x, ib0.y, ib0.z, ib0.w};
            const int   i1[NNZ] = {ia1.x, ia1.y, ia1.z, ia1.w, ib1.x, ib1.y, ib1.z, ib1.w};
            const float w0[NNZ] = {wa0.x, wa0.y, wa0.z, wa0.w, wb0.x, wb0.y, wb0.z, wb0.w};
            const float w1[NNZ] = {wa1.x, wa1.y, wa1.z, wa1.w, wb1.x, wb1.y, wb1.z, wb1.w};

            float4 acc0 = pe;
            float4 acc1 = pe;
            #pragma unroll
            for (int kk = 0; kk < NNZ; kk++) {
                float4 v0 = __ldg(val_tab + (size_t)i0[kk] * D4 + col4);
                float4 v1 = __ldg(val_tab + (size_t)i1[kk] * D4 + col4);
                acc0.x += w0[kk] * v0.x;  acc0.y += w0[kk] * v0.y;
                acc0.z += w0[kk] * v0.z;  acc0.w += w0[kk] * v0.w;
                acc1.x += w1[kk] * v1.x;  acc1.y += w1[kk] * v1.y;
                acc1.z += w1[kk] * v1.z;  acc1.w += w1[kk] * v1.w;
            }
            outsec[(size_t)b0 * D4 + col4] = acc0;
            outsec[(size_t)b1 * D4 + col4] = acc1;
        }
    }
}

extern "C" void kernel_launch(void* const* d_in, const int* in_sizes, int n_in,
                              void* d_out, int out_size) {
    const int*   node_idx = (const int*)  d_in[0];   // [16, 8192]
    const int*   edge_idx = (const int*)  d_in[1];   // [15, 8192]
    const int*   val_idx  = (const int*)  d_in[2];   // [131072, 8]
    const float* val_w    = (const float*)d_in[3];   // [131072, 8]
    const float* node_tab = (const float*)d_in[4];   // [128, 256]
    const float* edge_tab = (const float*)d_in[5];   // [32, 256]
    const float* val_tab  = (const float*)d_in[6];   // [10000, 256]
    float* out = (float*)d_out;                      // [47, 8192, 256]

    (void)in_sizes; (void)n_in; (void)out_size;

    pe_init_kernel<<<L_NODE, 128>>>();

    dim3 grid(BATCH / ROWS_PER_BLOCK, L_TOTAL);      // (512, 47)
    embed_kernel<<<grid, 256>>>(node_idx, edge_idx, val_idx, val_w,
                                (const float4*)node_tab,
                                (const float4*)edge_tab,
                                (const float4*)val_tab,
                                (float4*)out);
}